// round 2
// baseline (speedup 1.0000x reference)
#include <cuda_runtime.h>
#include <cuda_bf16.h>

#define BDIM 256
#define NROWS 4096
#define DCOLS 8192

__device__ float g_partials[NROWS];
__device__ unsigned int g_done_count;   // zero-initialized; self-resetting

__device__ __forceinline__ float smoothl1(float a, float b) {
    float d = a - b;
    float ad = fabsf(d);
    return (ad < 1.0f) ? (0.5f * d * d) : (ad - 0.5f);
}

__global__ __launch_bounds__(BDIM)
void mask_smoothl1_fused_kernel(const float* __restrict__ in,
                                const float* __restrict__ tgt,
                                const int* __restrict__ mask,
                                float* __restrict__ out) {
    const int row = blockIdx.x;
    const int m = mask[row];

    float block_sum = 0.0f;

    if (m != 0) {
        const float4* __restrict__ a =
            reinterpret_cast<const float4*>(in  + (size_t)row * DCOLS);
        const float4* __restrict__ b =
            reinterpret_cast<const float4*>(tgt + (size_t)row * DCOLS);

        float acc = 0.0f;
        #pragma unroll
        for (int it = 0; it < (DCOLS / 4) / BDIM; ++it) {
            int i = it * BDIM + threadIdx.x;
            float4 x = a[i];
            float4 y = b[i];
            acc += smoothl1(x.x, y.x);
            acc += smoothl1(x.y, y.y);
            acc += smoothl1(x.z, y.z);
            acc += smoothl1(x.w, y.w);
        }

        // warp reduce
        #pragma unroll
        for (int off = 16; off > 0; off >>= 1)
            acc += __shfl_xor_sync(0xFFFFFFFFu, acc, off);

        __shared__ float warp_sums[BDIM / 32];
        const int wid = threadIdx.x >> 5;
        const int lid = threadIdx.x & 31;
        if (lid == 0) warp_sums[wid] = acc;
        __syncthreads();

        if (wid == 0) {
            float v = (lid < BDIM / 32) ? warp_sums[lid] : 0.0f;
            #pragma unroll
            for (int off = 4; off > 0; off >>= 1)
                v += __shfl_xor_sync(0xFFFFFFFFu, v, off);
            block_sum = v * ((float)m / (float)DCOLS);
        }
    }

    // thread 0 publishes this block's partial
    if (threadIdx.x == 0)
        g_partials[row] = block_sum;   // 0.0f when masked out

    // last-block-done detection
    __shared__ bool s_is_last;
    if (threadIdx.x == 0) {
        __threadfence();
        unsigned int prev = atomicAdd(&g_done_count, 1u);
        s_is_last = (prev == NROWS - 1);
    }
    __syncthreads();

    if (!s_is_last) return;

    // ---- last block: reduce all partials in a fixed order (deterministic) ----
    if (threadIdx.x == 0) g_done_count = 0;   // reset for next graph replay

    float acc = 0.0f;
    #pragma unroll
    for (int it = 0; it < NROWS / BDIM; ++it)
        acc += g_partials[it * BDIM + threadIdx.x];

    #pragma unroll
    for (int off = 16; off > 0; off >>= 1)
        acc += __shfl_xor_sync(0xFFFFFFFFu, acc, off);

    __shared__ float fin_sums[BDIM / 32];
    const int wid = threadIdx.x >> 5;
    const int lid = threadIdx.x & 31;
    if (lid == 0) fin_sums[wid] = acc;
    __syncthreads();

    if (wid == 0) {
        float v = (lid < BDIM / 32) ? fin_sums[lid] : 0.0f;
        #pragma unroll
        for (int off = 4; off > 0; off >>= 1)
            v += __shfl_xor_sync(0xFFFFFFFFu, v, off);
        if (lid == 0) out[0] = v;
    }
}

extern "C" void kernel_launch(void* const* d_in, const int* in_sizes, int n_in,
                              void* d_out, int out_size) {
    const float* inputs  = (const float*)d_in[0];
    const float* targets = (const float*)d_in[1];
    const int*   mask    = (const int*)d_in[2];
    float* out = (float*)d_out;

    mask_smoothl1_fused_kernel<<<NROWS, BDIM>>>(inputs, targets, mask, out);
}

// round 5
// speedup vs baseline: 1.0106x; 1.0106x over previous
#include <cuda_runtime.h>
#include <cuda_bf16.h>

#define BDIM 256
#define NROWS 4096
#define DCOLS 8192
#define ROWS_PER_BLOCK 2
#define NBLOCKS (NROWS / ROWS_PER_BLOCK)   // 2048

__device__ float g_partials[NBLOCKS];
__device__ unsigned int g_done_count;      // zero-init; self-resetting

__device__ __forceinline__ float smoothl1(float a, float b) {
    float d = a - b;
    float ad = fabsf(d);
    return (ad < 1.0f) ? (0.5f * d * d) : (ad - 0.5f);
}

// Per-thread partial sum over one row, 4-deep load batching for MLP.
__device__ __forceinline__ float row_partial(const float* __restrict__ in,
                                             const float* __restrict__ tgt,
                                             int row, int tid) {
    const float4* __restrict__ A =
        reinterpret_cast<const float4*>(in  + (size_t)row * DCOLS);
    const float4* __restrict__ B =
        reinterpret_cast<const float4*>(tgt + (size_t)row * DCOLS);

    float acc = 0.0f;
    #pragma unroll
    for (int half = 0; half < 2; ++half) {
        float4 x[4], y[4];
        // front-batch 8 LDG.128 before any consume
        #pragma unroll
        for (int j = 0; j < 4; ++j) {
            int i = (half * 4 + j) * BDIM + tid;
            x[j] = A[i];
            y[j] = B[i];
        }
        #pragma unroll
        for (int j = 0; j < 4; ++j) {
            acc += smoothl1(x[j].x, y[j].x);
            acc += smoothl1(x[j].y, y[j].y);
            acc += smoothl1(x[j].z, y[j].z);
            acc += smoothl1(x[j].w, y[j].w);
        }
    }
    return acc;
}

__global__ __launch_bounds__(BDIM)
void mask_smoothl1_fused_kernel(const float* __restrict__ in,
                                const float* __restrict__ tgt,
                                const int* __restrict__ mask,
                                float* __restrict__ out) {
    const int bid = blockIdx.x;
    const int tid = threadIdx.x;

    // one 8B load covers both rows' masks (uniform across block -> broadcast)
    const int2 mm = reinterpret_cast<const int2*>(mask)[bid];
    const int r0 = bid * 2;

    float acc = 0.0f;
    if (mm.x != 0) acc += (float)mm.x * row_partial(in, tgt, r0,     tid);
    if (mm.y != 0) acc += (float)mm.y * row_partial(in, tgt, r0 + 1, tid);
    acc *= (1.0f / (float)DCOLS);

    // ---- block reduce ----
    #pragma unroll
    for (int off = 16; off > 0; off >>= 1)
        acc += __shfl_xor_sync(0xFFFFFFFFu, acc, off);

    __shared__ float warp_sums[BDIM / 32];
    const int wid = tid >> 5;
    const int lid = tid & 31;
    if (lid == 0) warp_sums[wid] = acc;
    __syncthreads();

    float block_sum = 0.0f;
    if (wid == 0) {
        float v = (lid < BDIM / 32) ? warp_sums[lid] : 0.0f;
        #pragma unroll
        for (int off = 4; off > 0; off >>= 1)
            v += __shfl_xor_sync(0xFFFFFFFFu, v, off);
        block_sum = v;
    }

    if (tid == 0)
        g_partials[bid] = block_sum;

    // ---- last-block-done detection ----
    __shared__ bool s_is_last;
    if (tid == 0) {
        __threadfence();
        unsigned int prev = atomicAdd(&g_done_count, 1u);
        s_is_last = (prev == NBLOCKS - 1);
    }
    __syncthreads();
    if (!s_is_last) return;

    if (tid == 0) g_done_count = 0;    // reset for next graph replay

    // ---- final deterministic reduce over 2048 partials ----
    float facc = 0.0f;
    #pragma unroll
    for (int it = 0; it < NBLOCKS / BDIM; ++it)
        facc += g_partials[it * BDIM + tid];

    #pragma unroll
    for (int off = 16; off > 0; off >>= 1)
        facc += __shfl_xor_sync(0xFFFFFFFFu, facc, off);

    __shared__ float fin_sums[BDIM / 32];
    if (lid == 0) fin_sums[wid] = facc;
    __syncthreads();

    if (wid == 0) {
        float v = (lid < BDIM / 32) ? fin_sums[lid] : 0.0f;
        #pragma unroll
        for (int off = 4; off > 0; off >>= 1)
            v += __shfl_xor_sync(0xFFFFFFFFu, v, off);
        if (lid == 0) out[0] = v;
    }
}

extern "C" void kernel_launch(void* const* d_in, const int* in_sizes, int n_in,
                              void* d_out, int out_size) {
    const float* inputs  = (const float*)d_in[0];
    const float* targets = (const float*)d_in[1];
    const int*   mask    = (const int*)d_in[2];
    float* out = (float*)d_out;

    mask_smoothl1_fused_kernel<<<NBLOCKS, BDIM>>>(inputs, targets, mask, out);
}